// round 4
// baseline (speedup 1.0000x reference)
#include <cuda_runtime.h>

#define BB 2
#define NN 65536
#define KK 16
#define DD 32
#define NPTS (BB*NN)          // 131072 points
#define WARPS_PER_BLOCK 8
#define THREADS (WARPS_PER_BLOCK*32)
#define GRID (NPTS/WARPS_PER_BLOCK)

// Scratch (no cudaMalloc allowed): ping-pong z buffers + residual state.
__device__ float g_za[NPTS*DD];
__device__ float g_zb[NPTS*DD];
__device__ float g_prev[NPTS*DD];
__device__ float g_acc [NPTS*DD];

__device__ __forceinline__ float lrelu(float v) { return v >= 0.f ? v : 0.2f*v; }

// K0: z0 = relu((x @ W2) * g2 + b2), warp per point, lane = output channel.
__global__ void __launch_bounds__(THREADS)
k_transform(const float* __restrict__ x,
            const float* __restrict__ W2,
            const float* __restrict__ g2,
            const float* __restrict__ b2)
{
    __shared__ float sW2[DD*DD];
    int tid = threadIdx.x;
    for (int i = tid; i < DD*DD; i += THREADS) sW2[i] = W2[i];
    __syncthreads();

    int lane = tid & 31;
    int pt   = blockIdx.x * WARPS_PER_BLOCK + (tid >> 5);
    float xv = x[(size_t)pt*DD + lane];       // coalesced row load
    float a  = 0.f;
    #pragma unroll
    for (int d = 0; d < DD; d++) {
        float xd = __shfl_sync(0xffffffffu, xv, d);
        a = fmaf(xd, sW2[d*DD + lane], a);
    }
    g_za[(size_t)pt*DD + lane] = fmaxf(fmaf(a, g2[lane], b2[lane]), 0.f);
}

// One "block" of the network, fused with the NEXT block's per-point transform.
// MODE 0: first block (x1) — init acc/prev.
// MODE 1: middle blocks (x2, x3) — residual with prev, accumulate.
// MODE 2: last block (x4) — final lrelu(acc + x4) to out, no tail.
// zflag: 0 -> read g_za / write g_zb ; 1 -> read g_zb / write g_za.
template<int MODE>
__global__ void __launch_bounds__(THREADS)
k_block(int zflag,
        const int*   __restrict__ idx,
        const float* __restrict__ W1,  const float* __restrict__ g1, const float* __restrict__ b1,
        const float* __restrict__ W2n, const float* __restrict__ g2n, const float* __restrict__ b2n,
        float* __restrict__ out)
{
    __shared__ float sW1[2*DD*DD];   // 8 KB
    __shared__ float sW2[DD*DD];     // 4 KB
    int tid = threadIdx.x;
    for (int i = tid; i < 2*DD*DD; i += THREADS) sW1[i] = W1[i];
    if (MODE != 2)
        for (int i = tid; i < DD*DD; i += THREADS) sW2[i] = W2n[i];
    __syncthreads();

    int lane = tid & 31;
    int pt   = blockIdx.x * WARPS_PER_BLOCK + (tid >> 5);
    int b    = pt >> 16;                         // N = 65536
    const float* z_in = zflag ? g_zb : g_za;
    float*       z_out = zflag ? g_za : g_zb;
    const float* zb = z_in + (size_t)b * NN * DD;

    // 16 neighbor indices for this point: lanes 0..15 load, broadcast via shfl.
    const int* ip = idx + (size_t)pt * KK;
    int myidx = (lane < KK) ? ip[lane] : 0;

    // Gather + max/mean over k. Each lane reads one channel; a warp reads one
    // full 128B row per neighbor (row-aligned). 16 independent loads -> MLP=16.
    float mx = -1e30f, sm = 0.f;
    #pragma unroll
    for (int k = 0; k < KK; k++) {
        int j = __shfl_sync(0xffffffffu, myidx, k);
        float v = __ldg(&zb[(size_t)j*DD + lane]);
        mx = fmaxf(mx, v);
        sm += v;
    }
    float mn = sm * (1.f/KK);

    // Second 1x1 conv: out[e] = sum_c mx_c*W1[c][e] + mn_c*W1[32+c][e]
    float o = 0.f;
    #pragma unroll
    for (int c = 0; c < DD; c++) {
        float a = __shfl_sync(0xffffffffu, mx, c);
        float m = __shfl_sync(0xffffffffu, mn, c);
        o = fmaf(a, sW1[c*DD + lane], o);
        o = fmaf(m, sW1[(DD+c)*DD + lane], o);
    }
    float xv = fmaf(o, g1[lane], b1[lane]);      // x_i value for this channel

    size_t off = (size_t)pt*DD + lane;
    float s;
    if (MODE == 0) {
        g_acc[off]  = xv;
        g_prev[off] = xv;
        s = xv;
    } else if (MODE == 1) {
        float p = g_prev[off];
        s = xv + p;
        g_acc[off] += xv;
        g_prev[off] = xv;
    } else {
        out[off] = lrelu(g_acc[off] + xv);       // lrelu(x1+x2+x3+x4)
        return;
    }

    // Fused next-block transform: z_next = relu((lrelu(s) @ W2n) * g2n + b2n)
    float t = lrelu(s);
    float a2 = 0.f;
    #pragma unroll
    for (int d = 0; d < DD; d++) {
        float td = __shfl_sync(0xffffffffu, t, d);
        a2 = fmaf(td, sW2[d*DD + lane], a2);
    }
    z_out[off] = fmaxf(fmaf(a2, g2n[lane], b2n[lane]), 0.f);
}

extern "C" void kernel_launch(void* const* d_in, const int* in_sizes, int n_in,
                              void* d_out, int out_size)
{
    const float* x   = (const float*)d_in[0];   // (2,65536,32)
    const int*   idx = (const int*)  d_in[1];   // (2,65536,16)
    const float* W2d = (const float*)d_in[2];   // (4,32,32)
    const float* g2  = (const float*)d_in[3];   // (4,32)
    const float* b2  = (const float*)d_in[4];   // (4,32)
    const float* W1d = (const float*)d_in[5];   // (4,64,32)
    const float* g1  = (const float*)d_in[6];   // (4,32)
    const float* b1  = (const float*)d_in[7];   // (4,32)
    float* out = (float*)d_out;

    dim3 blk(THREADS), grd(GRID);

    // z0 from block-0 transform
    k_transform<<<grd, blk>>>(x, W2d, g2, b2);

    // block 0: reads g_za, writes x1 state + z1 into g_zb (uses block-1 weights for tail)
    k_block<0><<<grd, blk>>>(0, idx,
                             W1d + 0*2048, g1 + 0*32, b1 + 0*32,
                             W2d + 1*1024, g2 + 1*32, b2 + 1*32, out);
    // block 1: reads g_zb, writes z2 into g_za (tail = block-2 weights)
    k_block<1><<<grd, blk>>>(1, idx,
                             W1d + 1*2048, g1 + 1*32, b1 + 1*32,
                             W2d + 2*1024, g2 + 2*32, b2 + 2*32, out);
    // block 2: reads g_za, writes z3 into g_zb (tail = block-3 weights)
    k_block<1><<<grd, blk>>>(0, idx,
                             W1d + 2*2048, g1 + 2*32, b1 + 2*32,
                             W2d + 3*1024, g2 + 3*32, b2 + 3*32, out);
    // block 3: reads g_zb, writes final output
    k_block<2><<<grd, blk>>>(1, idx,
                             W1d + 3*2048, g1 + 3*32, b1 + 3*32,
                             W2d, g2, b2, out);
}

// round 5
// speedup vs baseline: 1.7746x; 1.7746x over previous
#include <cuda_runtime.h>

#define BB 2
#define NN 65536
#define KK 16
#define DD 32
#define NPTS (BB*NN)              // 131072 points
#define PT_PER_WARP 4
#define WARPS_PER_BLOCK 8
#define THREADS (WARPS_PER_BLOCK*32)
#define GRID (NPTS/(WARPS_PER_BLOCK*PT_PER_WARP))   // 4096

// Scratch (no cudaMalloc allowed): ping-pong z buffers + residual state.
__device__ float g_za[NPTS*DD];
__device__ float g_zb[NPTS*DD];
__device__ float g_prev[NPTS*DD];
__device__ float g_acc [NPTS*DD];

__device__ __forceinline__ float lrelu1(float v) { return v >= 0.f ? v : 0.2f*v; }
__device__ __forceinline__ float4 lrelu4(float4 v) {
    return make_float4(lrelu1(v.x), lrelu1(v.y), lrelu1(v.z), lrelu1(v.w));
}
__device__ __forceinline__ float4 max4(float4 a, float4 b) {
    return make_float4(fmaxf(a.x,b.x), fmaxf(a.y,b.y), fmaxf(a.z,b.z), fmaxf(a.w,b.w));
}
__device__ __forceinline__ void add4(float4& a, float4 b) {
    a.x += b.x; a.y += b.y; a.z += b.z; a.w += b.w;
}
__device__ __forceinline__ void fma4(float4& o, float s, float4 w) {
    o.x = fmaf(s, w.x, o.x); o.y = fmaf(s, w.y, o.y);
    o.z = fmaf(s, w.z, o.z); o.w = fmaf(s, w.w, o.w);
}
// Broadcast component (c&3) of v held by lane (grp*8 + c/4). c is compile-time.
__device__ __forceinline__ float bcast(const float4& v, int c, int grp) {
    float r = (c&3)==0 ? v.x : (c&3)==1 ? v.y : (c&3)==2 ? v.z : v.w;
    return __shfl_sync(0xffffffffu, r, (grp<<3) + (c>>2));
}

// K0: z0 = relu((x @ W2) * g2 + b2). Warp handles 4 points, lane = 4 channels.
__global__ void __launch_bounds__(THREADS)
k_transform(const float* __restrict__ x,
            const float* __restrict__ W2,
            const float* __restrict__ g2,
            const float* __restrict__ b2)
{
    __shared__ float4 sW2[DD*8];              // W2 as rows of 8 float4
    int tid = threadIdx.x;
    for (int i = tid; i < DD*8; i += THREADS)
        sW2[i] = reinterpret_cast<const float4*>(W2)[i];
    __syncthreads();

    int lane = tid & 31, wid = tid >> 5;
    int grp = lane >> 3, sub = lane & 7;
    int pt  = (blockIdx.x * WARPS_PER_BLOCK + wid) * PT_PER_WARP + grp;

    float4 xv = __ldg(reinterpret_cast<const float4*>(x) + (size_t)pt*8 + sub);
    float4 a = make_float4(0.f,0.f,0.f,0.f);
    #pragma unroll
    for (int d = 0; d < DD; d++)
        fma4(a, bcast(xv, d, grp), sW2[d*8 + sub]);

    float4 gv = __ldg(reinterpret_cast<const float4*>(g2) + sub);
    float4 bv = __ldg(reinterpret_cast<const float4*>(b2) + sub);
    float4 z;
    z.x = fmaxf(fmaf(a.x, gv.x, bv.x), 0.f);
    z.y = fmaxf(fmaf(a.y, gv.y, bv.y), 0.f);
    z.z = fmaxf(fmaf(a.z, gv.z, bv.z), 0.f);
    z.w = fmaxf(fmaf(a.w, gv.w, bv.w), 0.f);
    reinterpret_cast<float4*>(g_za)[(size_t)pt*8 + sub] = z;
}

// One network block fused with the NEXT block's per-point transform.
// MODE 0: first block (init acc/prev). MODE 1: middle. MODE 2: last (write out).
template<int MODE>
__global__ void __launch_bounds__(THREADS)
k_block(int zflag,
        const int*   __restrict__ idx,
        const float* __restrict__ W1,  const float* __restrict__ g1,  const float* __restrict__ b1,
        const float* __restrict__ W2n, const float* __restrict__ g2n, const float* __restrict__ b2n,
        float* __restrict__ out)
{
    __shared__ float4 sW1[2*DD*8];            // 8 KB
    __shared__ float4 sW2[DD*8];              // 4 KB
    int tid = threadIdx.x;
    for (int i = tid; i < 2*DD*8; i += THREADS)
        sW1[i] = reinterpret_cast<const float4*>(W1)[i];
    if (MODE != 2)
        for (int i = tid; i < DD*8; i += THREADS)
            sW2[i] = reinterpret_cast<const float4*>(W2n)[i];
    __syncthreads();

    int lane = tid & 31, wid = tid >> 5;
    int grp = lane >> 3, sub = lane & 7;
    int base = (blockIdx.x * WARPS_PER_BLOCK + wid) * PT_PER_WARP;
    int pt   = base + grp;
    int b    = pt >> 16;                       // N = 65536
    const float* z_in  = zflag ? g_zb : g_za;
    float*       z_out = zflag ? g_za : g_zb;
    const float4* zb = reinterpret_cast<const float4*>(z_in + (size_t)b * NN * DD);

    // Load all 64 neighbor indices for the warp's 4 points: one int2 per lane.
    int2 myidx = __ldg(reinterpret_cast<const int2*>(idx + (size_t)base*KK) + lane);

    // Gather + max/mean over k. Per k: 1 SHFL (serves 4 points) + 1 LDG.128.
    float4 mx = make_float4(-1e30f,-1e30f,-1e30f,-1e30f);
    float4 sm = make_float4(0.f,0.f,0.f,0.f);
    #pragma unroll
    for (int k = 0; k < KK; k++) {
        int j = __shfl_sync(0xffffffffu, (k&1) ? myidx.y : myidx.x, (grp<<3) + (k>>1));
        float4 v = __ldg(zb + (size_t)j*8 + sub);
        mx = max4(mx, v);
        add4(sm, v);
    }
    float4 mn = make_float4(sm.x*(1.f/KK), sm.y*(1.f/KK), sm.z*(1.f/KK), sm.w*(1.f/KK));

    // Second 1x1 conv: o[e] = sum_c mx_c*W1[c][e] + mn_c*W1[32+c][e]
    float4 o = make_float4(0.f,0.f,0.f,0.f);
    #pragma unroll
    for (int c = 0; c < DD; c++) {
        float a = bcast(mx, c, grp);
        float m = bcast(mn, c, grp);
        fma4(o, a, sW1[c*8 + sub]);
        fma4(o, m, sW1[(DD+c)*8 + sub]);
    }
    float4 g1v = __ldg(reinterpret_cast<const float4*>(g1) + sub);
    float4 b1v = __ldg(reinterpret_cast<const float4*>(b1) + sub);
    float4 xv;
    xv.x = fmaf(o.x, g1v.x, b1v.x);
    xv.y = fmaf(o.y, g1v.y, b1v.y);
    xv.z = fmaf(o.z, g1v.z, b1v.z);
    xv.w = fmaf(o.w, g1v.w, b1v.w);

    size_t off = (size_t)pt*8 + sub;
    float4 s;
    if (MODE == 0) {
        reinterpret_cast<float4*>(g_acc)[off]  = xv;
        reinterpret_cast<float4*>(g_prev)[off] = xv;
        s = xv;
    } else if (MODE == 1) {
        float4 p = reinterpret_cast<float4*>(g_prev)[off];
        s = make_float4(xv.x+p.x, xv.y+p.y, xv.z+p.z, xv.w+p.w);
        float4 ac = reinterpret_cast<float4*>(g_acc)[off];
        add4(ac, xv);
        reinterpret_cast<float4*>(g_acc)[off]  = ac;
        reinterpret_cast<float4*>(g_prev)[off] = xv;
    } else {
        float4 ac = reinterpret_cast<float4*>(g_acc)[off];
        add4(ac, xv);
        reinterpret_cast<float4*>(out)[off] = lrelu4(ac);   // lrelu(x1+x2+x3+x4)
        return;
    }

    // Fused next-block transform: z_next = relu((lrelu(s) @ W2n) * g2n + b2n)
    float4 t = lrelu4(s);
    float4 a2 = make_float4(0.f,0.f,0.f,0.f);
    #pragma unroll
    for (int d = 0; d < DD; d++)
        fma4(a2, bcast(t, d, grp), sW2[d*8 + sub]);

    float4 g2v = __ldg(reinterpret_cast<const float4*>(g2n) + sub);
    float4 b2v = __ldg(reinterpret_cast<const float4*>(b2n) + sub);
    float4 z;
    z.x = fmaxf(fmaf(a2.x, g2v.x, b2v.x), 0.f);
    z.y = fmaxf(fmaf(a2.y, g2v.y, b2v.y), 0.f);
    z.z = fmaxf(fmaf(a2.z, g2v.z, b2v.z), 0.f);
    z.w = fmaxf(fmaf(a2.w, g2v.w, b2v.w), 0.f);
    reinterpret_cast<float4*>(z_out)[off] = z;
}

extern "C" void kernel_launch(void* const* d_in, const int* in_sizes, int n_in,
                              void* d_out, int out_size)
{
    const float* x   = (const float*)d_in[0];   // (2,65536,32)
    const int*   idx = (const int*)  d_in[1];   // (2,65536,16)
    const float* W2d = (const float*)d_in[2];   // (4,32,32)
    const float* g2  = (const float*)d_in[3];   // (4,32)
    const float* b2  = (const float*)d_in[4];   // (4,32)
    const float* W1d = (const float*)d_in[5];   // (4,64,32)
    const float* g1  = (const float*)d_in[6];   // (4,32)
    const float* b1  = (const float*)d_in[7];   // (4,32)
    float* out = (float*)d_out;

    dim3 blk(THREADS), grd(GRID);

    // z0 from block-0 transform
    k_transform<<<grd, blk>>>(x, W2d, g2, b2);

    // block 0: reads g_za, writes x1 state + z1 into g_zb (tail = block-1 weights)
    k_block<0><<<grd, blk>>>(0, idx,
                             W1d + 0*2048, g1 + 0*32, b1 + 0*32,
                             W2d + 1*1024, g2 + 1*32, b2 + 1*32, out);
    // block 1: reads g_zb, writes z2 into g_za (tail = block-2 weights)
    k_block<1><<<grd, blk>>>(1, idx,
                             W1d + 1*2048, g1 + 1*32, b1 + 1*32,
                             W2d + 2*1024, g2 + 2*32, b2 + 2*32, out);
    // block 2: reads g_za, writes z3 into g_zb (tail = block-3 weights)
    k_block<1><<<grd, blk>>>(0, idx,
                             W1d + 2*2048, g1 + 2*32, b1 + 2*32,
                             W2d + 3*1024, g2 + 3*32, b2 + 3*32, out);
    // block 3: reads g_zb, writes final output
    k_block<2><<<grd, blk>>>(1, idx,
                             W1d + 3*2048, g1 + 3*32, b1 + 3*32,
                             W2d, g2, b2, out);
}

// round 6
// speedup vs baseline: 2.3480x; 1.3231x over previous
#include <cuda_runtime.h>

#define BB 2
#define NN 65536
#define KK 16
#define DD 32
#define NPTS (BB*NN)                 // 131072 points
#define WARPS_PER_BLOCK 8
#define THREADS (WARPS_PER_BLOCK*32)
#define PTS_PER_WARP 16              // 8 spatial groups x 2 temporal sets
#define GRID (NPTS/(WARPS_PER_BLOCK*PTS_PER_WARP))   // 1024

// Scratch (no cudaMalloc allowed): ping-pong z buffers + residual state.
__device__ float g_za[NPTS*DD];
__device__ float g_zb[NPTS*DD];
__device__ float g_prev[NPTS*DD];
__device__ float g_acc [NPTS*DD];

__device__ __forceinline__ float lrelu1(float v) { return v >= 0.f ? v : 0.2f*v; }
__device__ __forceinline__ float4 lrelu4(float4 v) {
    return make_float4(lrelu1(v.x), lrelu1(v.y), lrelu1(v.z), lrelu1(v.w));
}
__device__ __forceinline__ float4 max4(float4 a, float4 b) {
    return make_float4(fmaxf(a.x,b.x), fmaxf(a.y,b.y), fmaxf(a.z,b.z), fmaxf(a.w,b.w));
}
__device__ __forceinline__ void add4(float4& a, float4 b) {
    a.x += b.x; a.y += b.y; a.z += b.z; a.w += b.w;
}
__device__ __forceinline__ void fma4(float4& o, float s, float4 w) {
    o.x = fmaf(s, w.x, o.x); o.y = fmaf(s, w.y, o.y);
    o.z = fmaf(s, w.z, o.z); o.w = fmaf(s, w.w, o.w);
}
__device__ __forceinline__ float4 affine4(float4 a, float4 g, float4 b) {
    return make_float4(fmaf(a.x,g.x,b.x), fmaf(a.y,g.y,b.y),
                       fmaf(a.z,g.z,b.z), fmaf(a.w,g.w,b.w));
}
__device__ __forceinline__ float4 relu4(float4 v) {
    return make_float4(fmaxf(v.x,0.f), fmaxf(v.y,0.f), fmaxf(v.z,0.f), fmaxf(v.w,0.f));
}
// Select element c (0..7) from a per-lane pair of float4 (compile-time c).
__device__ __forceinline__ float sel8(const float4& A, const float4& B, int c) {
    switch (c & 7) {
        case 0: return A.x;  case 1: return A.y;  case 2: return A.z;  case 3: return A.w;
        case 4: return B.x;  case 5: return B.y;  case 6: return B.z;  default: return B.w;
    }
}
// Broadcast channel c of this group's point: owner lane = grp*4 + c/8, element c%8.
__device__ __forceinline__ float bc8(const float4& A, const float4& B, int c, int grp) {
    return __shfl_sync(0xffffffffu, sel8(A, B, c), (grp << 2) + (c >> 3));
}
__device__ __forceinline__ int sel4i(const int4& v, int c) {
    return (c & 3) == 0 ? v.x : (c & 3) == 1 ? v.y : (c & 3) == 2 ? v.z : v.w;
}

// K0: z0 = relu((x @ W2) * g2 + b2). 16 pts/warp, 4 lanes/pt (2 float4 each).
__global__ void __launch_bounds__(THREADS)
k_transform(const float* __restrict__ x,
            const float* __restrict__ W2,
            const float* __restrict__ g2,
            const float* __restrict__ b2)
{
    __shared__ float4 sW2[DD*8];
    int tid = threadIdx.x;
    for (int i = tid; i < DD*8; i += THREADS)
        sW2[i] = reinterpret_cast<const float4*>(W2)[i];
    __syncthreads();

    int lane = tid & 31, wid = tid >> 5;
    int grp = lane >> 2, sub = lane & 3;
    int base = (blockIdx.x * WARPS_PER_BLOCK + wid) * PTS_PER_WARP;
    size_t o0 = (size_t)(base + grp)*8 + sub*2;
    size_t o1 = (size_t)(base + 8 + grp)*8 + sub*2;

    const float4* xf = reinterpret_cast<const float4*>(x);
    float4 x0a = __ldg(xf + o0), x0b = __ldg(xf + o0 + 1);
    float4 x1a = __ldg(xf + o1), x1b = __ldg(xf + o1 + 1);

    float4 a0a = {0,0,0,0}, a0b = {0,0,0,0}, a1a = {0,0,0,0}, a1b = {0,0,0,0};
    #pragma unroll
    for (int c = 0; c < DD; c++) {
        float4 w0 = sW2[c*8 + sub*2], w1 = sW2[c*8 + sub*2 + 1];
        float t0 = bc8(x0a, x0b, c, grp);
        float t1 = bc8(x1a, x1b, c, grp);
        fma4(a0a, t0, w0); fma4(a0b, t0, w1);
        fma4(a1a, t1, w0); fma4(a1b, t1, w1);
    }
    float4 gA = __ldg(reinterpret_cast<const float4*>(g2) + sub*2);
    float4 gB = __ldg(reinterpret_cast<const float4*>(g2) + sub*2 + 1);
    float4 bA = __ldg(reinterpret_cast<const float4*>(b2) + sub*2);
    float4 bB = __ldg(reinterpret_cast<const float4*>(b2) + sub*2 + 1);
    float4* za = reinterpret_cast<float4*>(g_za);
    za[o0]   = relu4(affine4(a0a, gA, bA));
    za[o0+1] = relu4(affine4(a0b, gB, bB));
    za[o1]   = relu4(affine4(a1a, gA, bA));
    za[o1+1] = relu4(affine4(a1b, gB, bB));
}

// One network block fused with the NEXT block's per-point transform.
// MODE 0: first (init acc/prev). MODE 1: middle. MODE 2: last (write out).
template<int MODE>
__global__ void __launch_bounds__(THREADS)
k_block(int zflag,
        const int*   __restrict__ idx,
        const float* __restrict__ W1,  const float* __restrict__ g1,  const float* __restrict__ b1,
        const float* __restrict__ W2n, const float* __restrict__ g2n, const float* __restrict__ b2n,
        float* __restrict__ out)
{
    __shared__ float4 sW1[2*DD*8];            // 8 KB
    __shared__ float4 sW2[DD*8];              // 4 KB
    int tid = threadIdx.x;
    for (int i = tid; i < 2*DD*8; i += THREADS)
        sW1[i] = reinterpret_cast<const float4*>(W1)[i];
    if (MODE != 2)
        for (int i = tid; i < DD*8; i += THREADS)
            sW2[i] = reinterpret_cast<const float4*>(W2n)[i];
    __syncthreads();

    int lane = tid & 31, wid = tid >> 5;
    int grp = lane >> 2, sub = lane & 3;
    int base = (blockIdx.x * WARPS_PER_BLOCK + wid) * PTS_PER_WARP;
    int b    = base >> 16;                     // all 16 pts share the batch
    const float* z_in  = zflag ? g_zb : g_za;
    float*       z_out = zflag ? g_za : g_zb;
    const float4* zb = reinterpret_cast<const float4*>(z_in + (size_t)b * NN * DD);

    // 256 neighbor indices for the warp's 16 points: two int4 per lane.
    const int4* ip = reinterpret_cast<const int4*>(idx + (size_t)base * KK);
    int4 iv0 = __ldg(ip + lane);        // points base..base+7
    int4 iv1 = __ldg(ip + 32 + lane);   // points base+8..base+15

    // Gather + max/mean over k for both sets. Per k: 2 SHFL + 4 LDG.128.
    float4 mx0a = {-1e30f,-1e30f,-1e30f,-1e30f}, mx0b = mx0a, mx1a = mx0a, mx1b = mx0a;
    float4 sm0a = {0,0,0,0}, sm0b = {0,0,0,0}, sm1a = {0,0,0,0}, sm1b = {0,0,0,0};
    #pragma unroll
    for (int k = 0; k < KK; k++) {
        int src = (grp << 2) + (k >> 2);
        int j0 = __shfl_sync(0xffffffffu, sel4i(iv0, k), src);
        int j1 = __shfl_sync(0xffffffffu, sel4i(iv1, k), src);
        float4 v;
        v = __ldg(zb + (size_t)j0*8 + sub*2);     mx0a = max4(mx0a, v); add4(sm0a, v);
        v = __ldg(zb + (size_t)j0*8 + sub*2 + 1); mx0b = max4(mx0b, v); add4(sm0b, v);
        v = __ldg(zb + (size_t)j1*8 + sub*2);     mx1a = max4(mx1a, v); add4(sm1a, v);
        v = __ldg(zb + (size_t)j1*8 + sub*2 + 1); mx1b = max4(mx1b, v); add4(sm1b, v);
    }
    const float s16 = 1.f/KK;
    sm0a.x*=s16; sm0a.y*=s16; sm0a.z*=s16; sm0a.w*=s16;
    sm0b.x*=s16; sm0b.y*=s16; sm0b.z*=s16; sm0b.w*=s16;
    sm1a.x*=s16; sm1a.y*=s16; sm1a.z*=s16; sm1a.w*=s16;
    sm1b.x*=s16; sm1b.y*=s16; sm1b.z*=s16; sm1b.w*=s16;

    // Second 1x1 conv. Weights loaded once per c, reused for both sets.
    float4 o0a = {0,0,0,0}, o0b = {0,0,0,0}, o1a = {0,0,0,0}, o1b = {0,0,0,0};
    #pragma unroll
    for (int c = 0; c < DD; c++) {
        float4 wa0 = sW1[c*8 + sub*2],        wa1 = sW1[c*8 + sub*2 + 1];
        float4 wb0 = sW1[(DD+c)*8 + sub*2],   wb1 = sW1[(DD+c)*8 + sub*2 + 1];
        float a0 = bc8(mx0a, mx0b, c, grp), m0 = bc8(sm0a, sm0b, c, grp);
        float a1 = bc8(mx1a, mx1b, c, grp), m1 = bc8(sm1a, sm1b, c, grp);
        fma4(o0a, a0, wa0); fma4(o0b, a0, wa1); fma4(o0a, m0, wb0); fma4(o0b, m0, wb1);
        fma4(o1a, a1, wa0); fma4(o1b, a1, wa1); fma4(o1a, m1, wb0); fma4(o1b, m1, wb1);
    }
    float4 g1A = __ldg(reinterpret_cast<const float4*>(g1) + sub*2);
    float4 g1B = __ldg(reinterpret_cast<const float4*>(g1) + sub*2 + 1);
    float4 b1A = __ldg(reinterpret_cast<const float4*>(b1) + sub*2);
    float4 b1B = __ldg(reinterpret_cast<const float4*>(b1) + sub*2 + 1);
    float4 x0a = affine4(o0a, g1A, b1A), x0b = affine4(o0b, g1B, b1B);
    float4 x1a = affine4(o1a, g1A, b1A), x1b = affine4(o1b, g1B, b1B);

    size_t o0 = (size_t)(base + grp)*8 + sub*2;
    size_t o1 = (size_t)(base + 8 + grp)*8 + sub*2;
    float4* accp  = reinterpret_cast<float4*>(g_acc);
    float4* prevp = reinterpret_cast<float4*>(g_prev);
    float4 s0a, s0b, s1a, s1b;
    if (MODE == 0) {
        accp[o0] = x0a; accp[o0+1] = x0b; accp[o1] = x1a; accp[o1+1] = x1b;
        prevp[o0] = x0a; prevp[o0+1] = x0b; prevp[o1] = x1a; prevp[o1+1] = x1b;
        s0a = x0a; s0b = x0b; s1a = x1a; s1b = x1b;
    } else if (MODE == 1) {
        float4 p;
        p = prevp[o0];   s0a = make_float4(x0a.x+p.x, x0a.y+p.y, x0a.z+p.z, x0a.w+p.w);
        p = prevp[o0+1]; s0b = make_float4(x0b.x+p.x, x0b.y+p.y, x0b.z+p.z, x0b.w+p.w);
        p = prevp[o1];   s1a = make_float4(x1a.x+p.x, x1a.y+p.y, x1a.z+p.z, x1a.w+p.w);
        p = prevp[o1+1]; s1b = make_float4(x1b.x+p.x, x1b.y+p.y, x1b.z+p.z, x1b.w+p.w);
        float4 ac;
        ac = accp[o0];   add4(ac, x0a); accp[o0]   = ac;
        ac = accp[o0+1]; add4(ac, x0b); accp[o0+1] = ac;
        ac = accp[o1];   add4(ac, x1a); accp[o1]   = ac;
        ac = accp[o1+1]; add4(ac, x1b); accp[o1+1] = ac;
        prevp[o0] = x0a; prevp[o0+1] = x0b; prevp[o1] = x1a; prevp[o1+1] = x1b;
    } else {
        float4* outp = reinterpret_cast<float4*>(out);
        float4 ac;
        ac = accp[o0];   add4(ac, x0a); outp[o0]   = lrelu4(ac);
        ac = accp[o0+1]; add4(ac, x0b); outp[o0+1] = lrelu4(ac);
        ac = accp[o1];   add4(ac, x1a); outp[o1]   = lrelu4(ac);
        ac = accp[o1+1]; add4(ac, x1b); outp[o1+1] = lrelu4(ac);
        return;
    }

    // Fused next-block transform: z_next = relu((lrelu(s) @ W2n) * g2n + b2n)
    float4 t0a = lrelu4(s0a), t0b = lrelu4(s0b), t1a = lrelu4(s1a), t1b = lrelu4(s1b);
    float4 a0a = {0,0,0,0}, a0b = {0,0,0,0}, a1a = {0,0,0,0}, a1b = {0,0,0,0};
    #pragma unroll
    for (int c = 0; c < DD; c++) {
        float4 w0 = sW2[c*8 + sub*2], w1 = sW2[c*8 + sub*2 + 1];
        float t0 = bc8(t0a, t0b, c, grp);
        float t1 = bc8(t1a, t1b, c, grp);
        fma4(a0a, t0, w0); fma4(a0b, t0, w1);
        fma4(a1a, t1, w0); fma4(a1b, t1, w1);
    }
    float4 g2A = __ldg(reinterpret_cast<const float4*>(g2n) + sub*2);
    float4 g2B = __ldg(reinterpret_cast<const float4*>(g2n) + sub*2 + 1);
    float4 b2A = __ldg(reinterpret_cast<const float4*>(b2n) + sub*2);
    float4 b2B = __ldg(reinterpret_cast<const float4*>(b2n) + sub*2 + 1);
    float4* zo = reinterpret_cast<float4*>(z_out);
    zo[o0]   = relu4(affine4(a0a, g2A, b2A));
    zo[o0+1] = relu4(affine4(a0b, g2B, b2B));
    zo[o1]   = relu4(affine4(a1a, g2A, b2A));
    zo[o1+1] = relu4(affine4(a1b, g2B, b2B));
}

extern "C" void kernel_launch(void* const* d_in, const int* in_sizes, int n_in,
                              void* d_out, int out_size)
{
    const float* x   = (const float*)d_in[0];   // (2,65536,32)
    const int*   idx = (const int*)  d_in[1];   // (2,65536,16)
    const float* W2d = (const float*)d_in[2];   // (4,32,32)
    const float* g2  = (const float*)d_in[3];   // (4,32)
    const float* b2  = (const float*)d_in[4];   // (4,32)
    const float* W1d = (const float*)d_in[5];   // (4,64,32)
    const float* g1  = (const float*)d_in[6];   // (4,32)
    const float* b1  = (const float*)d_in[7];   // (4,32)
    float* out = (float*)d_out;

    dim3 blk(THREADS), grd(GRID);

    // z0 from block-0 transform
    k_transform<<<grd, blk>>>(x, W2d, g2, b2);

    // block 0: reads g_za, writes x1 state + z1 into g_zb (tail = block-1 weights)
    k_block<0><<<grd, blk>>>(0, idx,
                             W1d + 0*2048, g1 + 0*32, b1 + 0*32,
                             W2d + 1*1024, g2 + 1*32, b2 + 1*32, out);
    // block 1: reads g_zb, writes z2 into g_za (tail = block-2 weights)
    k_block<1><<<grd, blk>>>(1, idx,
                             W1d + 1*2048, g1 + 1*32, b1 + 1*32,
                             W2d + 2*1024, g2 + 2*32, b2 + 2*32, out);
    // block 2: reads g_za, writes z3 into g_zb (tail = block-3 weights)
    k_block<1><<<grd, blk>>>(0, idx,
                             W1d + 2*2048, g1 + 2*32, b1 + 2*32,
                             W2d + 3*1024, g2 + 3*32, b2 + 3*32, out);
    // block 3: reads g_zb, writes final output
    k_block<2><<<grd, blk>>>(1, idx,
                             W1d + 3*2048, g1 + 3*32, b1 + 3*32,
                             W2d, g2, b2, out);
}

// round 7
// speedup vs baseline: 2.7291x; 1.1623x over previous
#include <cuda_runtime.h>

#define BB 2
#define NN 65536
#define KK 16
#define DD 32
#define NPTS (BB*NN)                 // 131072 points
#define WARPS_PER_BLOCK 8
#define THREADS (WARPS_PER_BLOCK*32)
#define SETS 4                       // temporal sets per warp
#define PTS_PER_WARP 16              // 4 spatial groups x 4 temporal sets
#define GRID (NPTS/(WARPS_PER_BLOCK*PTS_PER_WARP))   // 1024

// Scratch (no cudaMalloc allowed): ping-pong z buffers + residual state.
__device__ float g_za[NPTS*DD];
__device__ float g_zb[NPTS*DD];
__device__ float g_prev[NPTS*DD];
__device__ float g_acc [NPTS*DD];

__device__ __forceinline__ float lrelu1(float v) { return v >= 0.f ? v : 0.2f*v; }
__device__ __forceinline__ float4 lrelu4(float4 v) {
    return make_float4(lrelu1(v.x), lrelu1(v.y), lrelu1(v.z), lrelu1(v.w));
}
__device__ __forceinline__ float4 max4(float4 a, float4 b) {
    return make_float4(fmaxf(a.x,b.x), fmaxf(a.y,b.y), fmaxf(a.z,b.z), fmaxf(a.w,b.w));
}
__device__ __forceinline__ void add4(float4& a, float4 b) {
    a.x += b.x; a.y += b.y; a.z += b.z; a.w += b.w;
}
__device__ __forceinline__ void fma4(float4& o, float s, float4 w) {
    o.x = fmaf(s, w.x, o.x); o.y = fmaf(s, w.y, o.y);
    o.z = fmaf(s, w.z, o.z); o.w = fmaf(s, w.w, o.w);
}
__device__ __forceinline__ float4 affine4(float4 a, float4 g, float4 b) {
    return make_float4(fmaf(a.x,g.x,b.x), fmaf(a.y,g.y,b.y),
                       fmaf(a.z,g.z,b.z), fmaf(a.w,g.w,b.w));
}
__device__ __forceinline__ float4 relu4(float4 v) {
    return make_float4(fmaxf(v.x,0.f), fmaxf(v.y,0.f), fmaxf(v.z,0.f), fmaxf(v.w,0.f));
}
__device__ __forceinline__ float sel4(const float4& v, int c) {
    return (c&3)==0 ? v.x : (c&3)==1 ? v.y : (c&3)==2 ? v.z : v.w;
}
__device__ __forceinline__ int sel4i(const int4& v, int c) {
    return (c&3)==0 ? v.x : (c&3)==1 ? v.y : (c&3)==2 ? v.z : v.w;
}
// Broadcast channel c (0..31) of this group's point: owner lane grp*8 + c/4.
__device__ __forceinline__ float bc(const float4& v, int c, int grp) {
    return __shfl_sync(0xffffffffu, sel4(v, c), (grp<<3) + (c>>2));
}

// K0: z0 = relu((x @ W2) * g2 + b2). 16 pts/warp: 4 groups x 4 sets, 8 lanes/pt.
__global__ void __launch_bounds__(THREADS)
k_transform(const float* __restrict__ x,
            const float* __restrict__ W2,
            const float* __restrict__ g2,
            const float* __restrict__ b2)
{
    __shared__ float4 sW2[DD*8];
    int tid = threadIdx.x;
    for (int i = tid; i < DD*8; i += THREADS)
        sW2[i] = reinterpret_cast<const float4*>(W2)[i];
    __syncthreads();

    int lane = tid & 31, wid = tid >> 5;
    int grp = lane >> 3, sub = lane & 7;
    int base = (blockIdx.x * WARPS_PER_BLOCK + wid) * PTS_PER_WARP;
    const float4* xf = reinterpret_cast<const float4*>(x);

    size_t off[SETS];
    float4 xv[SETS], a[SETS];
    #pragma unroll
    for (int s = 0; s < SETS; s++) {
        off[s] = (size_t)(base + s*4 + grp)*8 + sub;
        xv[s]  = __ldg(xf + off[s]);
        a[s]   = make_float4(0.f,0.f,0.f,0.f);
    }
    #pragma unroll
    for (int c = 0; c < DD; c++) {
        float4 w = sW2[c*8 + sub];
        #pragma unroll
        for (int s = 0; s < SETS; s++)
            fma4(a[s], bc(xv[s], c, grp), w);
    }
    float4 gv = __ldg(reinterpret_cast<const float4*>(g2) + sub);
    float4 bv = __ldg(reinterpret_cast<const float4*>(b2) + sub);
    float4* za = reinterpret_cast<float4*>(g_za);
    #pragma unroll
    for (int s = 0; s < SETS; s++)
        za[off[s]] = relu4(affine4(a[s], gv, bv));
}

// One network block fused with the NEXT block's per-point transform.
// MODE 0: first (init acc/prev). MODE 1: middle. MODE 2: last (write out).
template<int MODE>
__global__ void __launch_bounds__(THREADS)
k_block(int zflag,
        const int*   __restrict__ idx,
        const float* __restrict__ W1,  const float* __restrict__ g1,  const float* __restrict__ b1,
        const float* __restrict__ W2n, const float* __restrict__ g2n, const float* __restrict__ b2n,
        float* __restrict__ out)
{
    __shared__ float4 sW1[2*DD*8];            // 8 KB
    __shared__ float4 sW2[DD*8];              // 4 KB
    int tid = threadIdx.x;
    for (int i = tid; i < 2*DD*8; i += THREADS)
        sW1[i] = reinterpret_cast<const float4*>(W1)[i];
    if (MODE != 2)
        for (int i = tid; i < DD*8; i += THREADS)
            sW2[i] = reinterpret_cast<const float4*>(W2n)[i];
    __syncthreads();

    int lane = tid & 31, wid = tid >> 5;
    int grp = lane >> 3, sub = lane & 7;
    int base = (blockIdx.x * WARPS_PER_BLOCK + wid) * PTS_PER_WARP;
    int b    = base >> 16;                     // all 16 pts share the batch
    const float* z_in  = zflag ? g_zb : g_za;
    float*       z_out = zflag ? g_za : g_zb;
    const float4* zb = reinterpret_cast<const float4*>(z_in + (size_t)b * NN * DD);

    // 256 neighbor indices for the warp's 16 points: two int4 per lane.
    // iv0 = points base..base+7 (sets 0,1); iv1 = points base+8..15 (sets 2,3).
    const int4* ip = reinterpret_cast<const int4*>(idx + (size_t)base * KK);
    int4 iv0 = __ldg(ip + lane);
    int4 iv1 = __ldg(ip + 32 + lane);

    // Gather + max/mean over k. Per k per set: 1 SHFL + 1 LDG.128.
    // Each LDG.128 covers a point's FULL 128B row with 8 lanes -> 1 wavefront/line.
    float4 mx[SETS], sm[SETS];
    #pragma unroll
    for (int s = 0; s < SETS; s++) {
        mx[s] = make_float4(-1e30f,-1e30f,-1e30f,-1e30f);
        sm[s] = make_float4(0.f,0.f,0.f,0.f);
    }
    #pragma unroll
    for (int k = 0; k < KK; k++) {
        #pragma unroll
        for (int s = 0; s < SETS; s++) {
            // point p_local = s*4+grp; int4 slot = p_local*4 + k/4, element k%4
            int slot = ((s & 1) << 4) + (grp << 2) + (k >> 2);
            int j = __shfl_sync(0xffffffffu, sel4i((s & 2) ? iv1 : iv0, k), slot);
            float4 v = __ldg(zb + (size_t)j*8 + sub);
            mx[s] = max4(mx[s], v);
            add4(sm[s], v);
        }
    }
    const float r16 = 1.f/KK;
    #pragma unroll
    for (int s = 0; s < SETS; s++) {
        sm[s].x *= r16; sm[s].y *= r16; sm[s].z *= r16; sm[s].w *= r16;
    }

    // Second 1x1 conv. Weight rows loaded from shared once per c (broadcast),
    // reused across all 4 sets.
    float4 o[SETS];
    #pragma unroll
    for (int s = 0; s < SETS; s++) o[s] = make_float4(0.f,0.f,0.f,0.f);
    #pragma unroll
    for (int c = 0; c < DD; c++) {
        float4 wa = sW1[c*8 + sub];
        float4 wb = sW1[(DD + c)*8 + sub];
        #pragma unroll
        for (int s = 0; s < SETS; s++) {
            fma4(o[s], bc(mx[s], c, grp), wa);
            fma4(o[s], bc(sm[s], c, grp), wb);
        }
    }
    float4 g1v = __ldg(reinterpret_cast<const float4*>(g1) + sub);
    float4 b1v = __ldg(reinterpret_cast<const float4*>(b1) + sub);
    float4 xv[SETS];
    size_t off[SETS];
    #pragma unroll
    for (int s = 0; s < SETS; s++) {
        xv[s]  = affine4(o[s], g1v, b1v);
        off[s] = (size_t)(base + s*4 + grp)*8 + sub;
    }

    float4* accp  = reinterpret_cast<float4*>(g_acc);
    float4* prevp = reinterpret_cast<float4*>(g_prev);
    float4 sres[SETS];
    if (MODE == 0) {
        #pragma unroll
        for (int s = 0; s < SETS; s++) {
            accp[off[s]]  = xv[s];
            prevp[off[s]] = xv[s];
            sres[s] = xv[s];
        }
    } else if (MODE == 1) {
        #pragma unroll
        for (int s = 0; s < SETS; s++) {
            float4 p = prevp[off[s]];
            sres[s] = make_float4(xv[s].x+p.x, xv[s].y+p.y, xv[s].z+p.z, xv[s].w+p.w);
            float4 ac = accp[off[s]];
            add4(ac, xv[s]);
            accp[off[s]]  = ac;
            prevp[off[s]] = xv[s];
        }
    } else {
        float4* outp = reinterpret_cast<float4*>(out);
        #pragma unroll
        for (int s = 0; s < SETS; s++) {
            float4 ac = accp[off[s]];
            add4(ac, xv[s]);
            outp[off[s]] = lrelu4(ac);         // lrelu(x1+x2+x3+x4)
        }
        return;
    }

    // Fused next-block transform: z_next = relu((lrelu(s) @ W2n) * g2n + b2n)
    float4 t[SETS], a2[SETS];
    #pragma unroll
    for (int s = 0; s < SETS; s++) {
        t[s]  = lrelu4(sres[s]);
        a2[s] = make_float4(0.f,0.f,0.f,0.f);
    }
    #pragma unroll
    for (int c = 0; c < DD; c++) {
        float4 w = sW2[c*8 + sub];
        #pragma unroll
        for (int s = 0; s < SETS; s++)
            fma4(a2[s], bc(t[s], c, grp), w);
    }
    float4 g2v = __ldg(reinterpret_cast<const float4*>(g2n) + sub);
    float4 b2v = __ldg(reinterpret_cast<const float4*>(b2n) + sub);
    float4* zo = reinterpret_cast<float4*>(z_out);
    #pragma unroll
    for (int s = 0; s < SETS; s++)
        zo[off[s]] = relu4(affine4(a2[s], g2v, b2v));
}

extern "C" void kernel_launch(void* const* d_in, const int* in_sizes, int n_in,
                              void* d_out, int out_size)
{
    const float* x   = (const float*)d_in[0];   // (2,65536,32)
    const int*   idx = (const int*)  d_in[1];   // (2,65536,16)
    const float* W2d = (const float*)d_in[2];   // (4,32,32)
    const float* g2  = (const float*)d_in[3];   // (4,32)
    const float* b2  = (const float*)d_in[4];   // (4,32)
    const float* W1d = (const float*)d_in[5];   // (4,64,32)
    const float* g1  = (const float*)d_in[6];   // (4,32)
    const float* b1  = (const float*)d_in[7];   // (4,32)
    float* out = (float*)d_out;

    dim3 blk(THREADS), grd(GRID);

    // z0 from block-0 transform
    k_transform<<<grd, blk>>>(x, W2d, g2, b2);

    // block 0: reads g_za, writes x1 state + z1 into g_zb (tail = block-1 weights)
    k_block<0><<<grd, blk>>>(0, idx,
                             W1d + 0*2048, g1 + 0*32, b1 + 0*32,
                             W2d + 1*1024, g2 + 1*32, b2 + 1*32, out);
    // block 1: reads g_zb, writes z2 into g_za (tail = block-2 weights)
    k_block<1><<<grd, blk>>>(1, idx,
                             W1d + 1*2048, g1 + 1*32, b1 + 1*32,
                             W2d + 2*1024, g2 + 2*32, b2 + 2*32, out);
    // block 2: reads g_za, writes z3 into g_zb (tail = block-3 weights)
    k_block<1><<<grd, blk>>>(0, idx,
                             W1d + 2*2048, g1 + 2*32, b1 + 2*32,
                             W2d + 3*1024, g2 + 3*32, b2 + 3*32, out);
    // block 3: reads g_zb, writes final output
    k_block<2><<<grd, blk>>>(1, idx,
                             W1d + 3*2048, g1 + 3*32, b1 + 3*32,
                             W2d, g2, b2, out);
}